// round 2
// baseline (speedup 1.0000x reference)
#include <cuda_runtime.h>
#include <cuda_bf16.h>
#include <math.h>

#define Nn 10000
#define Ee 160000
#define HID 256
#define HEADS 8
#define Cc 32
#define Tt 5
#define EDGE_DIM 9

// ---------------- scratch (static device globals; no allocation) ----------------
__device__ float g_ea[Ee * EDGE_DIM];
__device__ float g_h[Nn * HID];
__device__ float g_xl[Nn * HID];
__device__ float g_xr[Nn * HID];
__device__ float g_out[Nn * HID];
__device__ float g_logits[Ee * HEADS];
__device__ int   g_cnt[Nn + 1];
__device__ int   g_off[Nn + 1];
__device__ int   g_cur[Nn];
__device__ int   g_elist[Ee];
__device__ double g_red[512];
__device__ float g_bnp[512];   // per-channel scale/shift
__device__ float g_eap[2 * EDGE_DIM];

// ---------------- utility zero kernels ----------------
__global__ void zero_red_k() { int i = threadIdx.x; if (i < 512) g_red[i] = 0.0; }
__global__ void zero_cnt_k() { int i = blockIdx.x * 256 + threadIdx.x; if (i <= Nn) g_cnt[i] = 0; }

// ---------------- edge-attr normalization ----------------
__global__ void ea_stats_k(const float* __restrict__ ea) {
    __shared__ double ss[EDGE_DIM], ss2[EDGE_DIM];
    if (threadIdx.x < EDGE_DIM) { ss[threadIdx.x] = 0.0; ss2[threadIdx.x] = 0.0; }
    __syncthreads();
    double ls[EDGE_DIM] = {0}, ls2[EDGE_DIM] = {0};
    for (int e = blockIdx.x * blockDim.x + threadIdx.x; e < Ee; e += gridDim.x * blockDim.x) {
        #pragma unroll
        for (int k = 0; k < EDGE_DIM; k++) {
            float x = ea[e * EDGE_DIM + k];
            ls[k] += x; ls2[k] += (double)x * x;
        }
    }
    #pragma unroll
    for (int k = 0; k < EDGE_DIM; k++) { atomicAdd(&ss[k], ls[k]); atomicAdd(&ss2[k], ls2[k]); }
    __syncthreads();
    if (threadIdx.x < EDGE_DIM) {
        atomicAdd(&g_red[threadIdx.x], ss[threadIdx.x]);
        atomicAdd(&g_red[256 + threadIdx.x], ss2[threadIdx.x]);
    }
}

__global__ void ea_final_k() {
    int c = threadIdx.x;
    if (c < EDGE_DIM) {
        double mu = g_red[c] / (double)Ee;
        double var = g_red[256 + c] / (double)Ee - mu * mu;
        double sd = sqrt(var > 0.0 ? var : 0.0);
        g_eap[c] = (float)mu;
        g_eap[EDGE_DIM + c] = (float)(1.0 / (sd + 1e-8));
    }
}

__global__ void ea_norm_k(const float* __restrict__ ea) {
    int idx = blockIdx.x * 256 + threadIdx.x;
    if (idx < Ee * EDGE_DIM) {
        int c = idx % EDGE_DIM;
        g_ea[idx] = (ea[idx] - g_eap[c]) * g_eap[EDGE_DIM + c];
    }
}

// ---------------- lift: h = relu(x @ W(10x256) + b) ----------------
__global__ void lift_k(const float* __restrict__ x, const float* __restrict__ W,
                       const float* __restrict__ b) {
    int n = blockIdx.x;
    int c = threadIdx.x;
    float acc = b[c];
    #pragma unroll
    for (int k = 0; k < 10; k++) acc += x[n * 10 + k] * W[k * HID + c];
    g_h[n * HID + c] = fmaxf(acc, 0.f);
}

// ---------------- CSR build ----------------
__global__ void hist_k(const int* __restrict__ ei) {
    int e = blockIdx.x * 256 + threadIdx.x;
    if (e < Ee) atomicAdd(&g_cnt[ei[Ee + e]], 1);
}

__global__ void scan_k() {
    __shared__ int partial[1024];
    int tid = threadIdx.x;
    const int PER = 10;  // 1024*10 >= 10000
    int base = tid * PER;
    int loc[PER];
    int s = 0;
    #pragma unroll
    for (int i = 0; i < PER; i++) {
        int n = base + i;
        int v = (n < Nn) ? g_cnt[n] : 0;
        loc[i] = s; s += v;
    }
    partial[tid] = s;
    __syncthreads();
    for (int off = 1; off < 1024; off <<= 1) {
        int v = (tid >= off) ? partial[tid - off] : 0;
        __syncthreads();
        partial[tid] += v;
        __syncthreads();
    }
    int offset = (tid > 0) ? partial[tid - 1] : 0;
    #pragma unroll
    for (int i = 0; i < PER; i++) {
        int n = base + i;
        if (n < Nn) { g_off[n] = offset + loc[i]; g_cur[n] = offset + loc[i]; }
    }
    if (tid == 1023) g_off[Nn] = partial[1023];
}

__global__ void fill_k(const int* __restrict__ ei) {
    int e = blockIdx.x * 256 + threadIdx.x;
    if (e < Ee) {
        int pos = atomicAdd(&g_cur[ei[Ee + e]], 1);
        g_elist[pos] = e;
    }
}

// ---------------- fp32 GEMM: Y[M,256] = A[M,256] @ B[256,256] + bias ----------------
__global__ void gemm256_k(const float* __restrict__ A, const float* __restrict__ B,
                          const float* __restrict__ bias, float* __restrict__ Y, int M) {
    __shared__ float As[16][65];
    __shared__ float Bs[16][68];
    const int bm = blockIdx.x * 64, bn = blockIdx.y * 64;
    const int tid = threadIdx.x;
    const int tx = tid & 15, ty = tid >> 4;
    const int arow = tid >> 2, acol = (tid & 3) * 4;
    const int brow = tid >> 4, bcol = (tid & 15) * 4;
    float acc[4][4];
    #pragma unroll
    for (int i = 0; i < 4; i++)
        #pragma unroll
        for (int j = 0; j < 4; j++) acc[i][j] = 0.f;

    for (int k0 = 0; k0 < 256; k0 += 16) {
        float4 av = make_float4(0.f, 0.f, 0.f, 0.f);
        if (bm + arow < M)
            av = *reinterpret_cast<const float4*>(&A[(bm + arow) * 256 + k0 + acol]);
        As[acol + 0][arow] = av.x; As[acol + 1][arow] = av.y;
        As[acol + 2][arow] = av.z; As[acol + 3][arow] = av.w;
        float4 bv = *reinterpret_cast<const float4*>(&B[(k0 + brow) * 256 + bn + bcol]);
        Bs[brow][bcol + 0] = bv.x; Bs[brow][bcol + 1] = bv.y;
        Bs[brow][bcol + 2] = bv.z; Bs[brow][bcol + 3] = bv.w;
        __syncthreads();
        #pragma unroll
        for (int kk = 0; kk < 16; kk++) {
            float ra[4], rb[4];
            #pragma unroll
            for (int i = 0; i < 4; i++) ra[i] = As[kk][ty * 4 + i];
            #pragma unroll
            for (int j = 0; j < 4; j++) rb[j] = Bs[kk][tx * 4 + j];
            #pragma unroll
            for (int i = 0; i < 4; i++)
                #pragma unroll
                for (int j = 0; j < 4; j++) acc[i][j] += ra[i] * rb[j];
        }
        __syncthreads();
    }
    #pragma unroll
    for (int i = 0; i < 4; i++) {
        int row = bm + ty * 4 + i;
        if (row < M) {
            #pragma unroll
            for (int j = 0; j < 4; j++)
                Y[row * 256 + bn + tx * 4 + j] = acc[i][j] + bias[bn + tx * 4 + j];
        }
    }
}

// ---------------- edge logits: warp per edge ----------------
__global__ void edge_logits_k(const int* __restrict__ ei,
                              const float* __restrict__ We, const float* __restrict__ att) {
    __shared__ float sWe[EDGE_DIM * HID];
    __shared__ float sAtt[HID];
    int tid = threadIdx.x;
    for (int i = tid; i < EDGE_DIM * HID; i += 256) sWe[i] = We[i];
    sAtt[tid] = att[tid];
    __syncthreads();
    int warp = tid >> 5, lane = tid & 31;
    int e = blockIdx.x * 8 + warp;
    if (e >= Ee) return;
    int src = ei[e], dst = ei[Ee + e];
    float a9 = (lane < EDGE_DIM) ? g_ea[e * EDGE_DIM + lane] : 0.f;
    float p[8];
    #pragma unroll
    for (int j = 0; j < 8; j++) {
        int ch = j * 32 + lane;
        float xe = 0.f;
        #pragma unroll
        for (int k = 0; k < EDGE_DIM; k++)
            xe += __shfl_sync(0xffffffffu, a9, k) * sWe[k * HID + ch];
        float v = g_xl[src * HID + ch] + g_xr[dst * HID + ch] + xe;
        v = (v > 0.f) ? v : 0.2f * v;
        p[j] = v * sAtt[j * 32 + lane];
    }
    #pragma unroll
    for (int off = 16; off; off >>= 1)
        #pragma unroll
        for (int j = 0; j < 8; j++) p[j] += __shfl_xor_sync(0xffffffffu, p[j], off);
    if (lane == 0) {
        #pragma unroll
        for (int j = 0; j < 8; j++) g_logits[e * 8 + j] = p[j];
    }
}

// ---------------- segment softmax + aggregate: warp per (node, head) ----------------
__global__ void attn_agg_k(const int* __restrict__ ei, const float* __restrict__ bias) {
    int n = blockIdx.x;
    int h = threadIdx.x >> 5, lane = threadIdx.x & 31;
    int start = g_off[n], deg = g_off[n + 1] - start;
    int oidx = n * HID + h * 32 + lane;
    if (deg == 0) { g_out[oidx] = bias[h * 32 + lane]; return; }
    float m = -INFINITY;
    for (int i = lane; i < deg; i += 32)
        m = fmaxf(m, g_logits[g_elist[start + i] * 8 + h]);
    #pragma unroll
    for (int off = 16; off; off >>= 1) m = fmaxf(m, __shfl_xor_sync(0xffffffffu, m, off));
    float ssum = 0.f;
    for (int i = lane; i < deg; i += 32)
        ssum += expf(g_logits[g_elist[start + i] * 8 + h] - m);
    #pragma unroll
    for (int off = 16; off; off >>= 1) ssum += __shfl_xor_sync(0xffffffffu, ssum, off);
    float inv = 1.f / (ssum + 1e-16f);
    float acc = 0.f;
    for (int i = 0; i < deg; i++) {
        int e = g_elist[start + i];
        float w = expf(g_logits[e * 8 + h] - m) * inv;
        acc += w * g_xl[ei[e] * HID + h * 32 + lane];
    }
    g_out[oidx] = acc + bias[h * 32 + lane];
}

// ---------------- BatchNorm ----------------
__global__ void bn_stats_k(const float* __restrict__ v) {
    int c = threadIdx.x;
    double s = 0.0, s2 = 0.0;
    for (int n = blockIdx.x; n < Nn; n += gridDim.x) {
        float x = v[n * HID + c];
        s += x; s2 += (double)x * x;
    }
    atomicAdd(&g_red[c], s);
    atomicAdd(&g_red[256 + c], s2);
}

__global__ void bn_final_k(const float* __restrict__ gamma, const float* __restrict__ beta) {
    int c = threadIdx.x;
    double mu = g_red[c] / (double)Nn;
    double var = g_red[256 + c] / (double)Nn - mu * mu;
    float scale = gamma[c] * rsqrtf((float)var + 1e-5f);
    g_bnp[c] = scale;
    g_bnp[256 + c] = beta[c] - (float)mu * scale;
}

// act: 0 = elu, 1 = relu
__global__ void bn_apply_k(const float* __restrict__ v, float* __restrict__ o, int act) {
    int c = threadIdx.x;
    int idx = blockIdx.x * HID + c;
    float y = v[idx] * g_bnp[c] + g_bnp[256 + c];
    o[idx] = act ? fmaxf(y, 0.f) : ((y > 0.f) ? y : expm1f(y));
}

// ---------------- final projection: [N,256] @ [256,3] + b ----------------
__global__ void proj3_k(const float* __restrict__ W, const float* __restrict__ b,
                        float* __restrict__ out) {
    int idx = blockIdx.x * 256 + threadIdx.x;
    if (idx >= Nn * 3) return;
    int n = idx / 3, o = idx % 3;
    float acc = b[o];
    const float* hrow = &g_h[n * HID];
    #pragma unroll 8
    for (int k = 0; k < HID; k++) acc += hrow[k] * W[k * 3 + o];
    out[idx] = acc;
}

// ---------------- launch ----------------
extern "C" void kernel_launch(void* const* d_in, const int* in_sizes, int n_in,
                              void* d_out, int out_size) {
    const float* x         = (const float*)d_in[0];
    const float* edge_attr = (const float*)d_in[1];
    const int*   ei        = (const int*)  d_in[2];
    const float* lift_W    = (const float*)d_in[3];
    const float* lift_b    = (const float*)d_in[4];
    const float* Wl        = (const float*)d_in[5];
    const float* bl        = (const float*)d_in[6];
    const float* Wr        = (const float*)d_in[7];
    const float* br        = (const float*)d_in[8];
    const float* We        = (const float*)d_in[9];
    const float* att       = (const float*)d_in[10];
    const float* conv_bias = (const float*)d_in[11];
    const float* bn_gamma  = (const float*)d_in[12];
    const float* bn_beta   = (const float*)d_in[13];
    const float* p1_W      = (const float*)d_in[14];
    const float* p1_b      = (const float*)d_in[15];
    const float* pbn1_g    = (const float*)d_in[16];
    const float* pbn1_b    = (const float*)d_in[17];
    const float* p2_W      = (const float*)d_in[18];
    const float* p2_b      = (const float*)d_in[19];
    const float* pbn2_g    = (const float*)d_in[20];
    const float* pbn2_b    = (const float*)d_in[21];
    const float* p3_W      = (const float*)d_in[22];
    const float* p3_b      = (const float*)d_in[23];
    float* out = (float*)d_out;

    float* d_h   = nullptr; float* d_xl = nullptr; float* d_xr = nullptr; float* d_o = nullptr;
    cudaGetSymbolAddress((void**)&d_h,  g_h);
    cudaGetSymbolAddress((void**)&d_xl, g_xl);
    cudaGetSymbolAddress((void**)&d_xr, g_xr);
    cudaGetSymbolAddress((void**)&d_o,  g_out);

    dim3 ggrid((Nn + 63) / 64, 4);

    // edge-attr normalization
    zero_red_k<<<1, 512>>>();
    ea_stats_k<<<64, 256>>>(edge_attr);
    ea_final_k<<<1, 32>>>();
    ea_norm_k<<<(Ee * EDGE_DIM + 255) / 256, 256>>>(edge_attr);

    // lift
    lift_k<<<Nn, HID>>>(x, lift_W, lift_b);

    // CSR by destination
    zero_cnt_k<<<(Nn + 256) / 256, 256>>>();
    hist_k<<<Ee / 256, 256>>>(ei);
    scan_k<<<1, 1024>>>();
    fill_k<<<Ee / 256, 256>>>(ei);

    for (int t = 0; t < Tt; t++) {
        gemm256_k<<<ggrid, 256>>>(d_h, Wl + t * HID * HID, bl + t * HID, d_xl, Nn);
        gemm256_k<<<ggrid, 256>>>(d_h, Wr + t * HID * HID, br + t * HID, d_xr, Nn);
        edge_logits_k<<<Ee / 8, 256>>>(ei, We + t * EDGE_DIM * HID, att + t * HEADS * Cc);
        attn_agg_k<<<Nn, 256>>>(ei, conv_bias + t * HID);
        zero_red_k<<<1, 512>>>();
        bn_stats_k<<<80, 256>>>(d_o);
        bn_final_k<<<1, 256>>>(bn_gamma + t * HID, bn_beta + t * HID);
        bn_apply_k<<<Nn, HID>>>(d_o, d_h, 0);
    }

    // projection MLP
    gemm256_k<<<ggrid, 256>>>(d_h, p1_W, p1_b, d_o, Nn);
    zero_red_k<<<1, 512>>>();
    bn_stats_k<<<80, 256>>>(d_o);
    bn_final_k<<<1, 256>>>(pbn1_g, pbn1_b);
    bn_apply_k<<<Nn, HID>>>(d_o, d_h, 1);

    gemm256_k<<<ggrid, 256>>>(d_h, p2_W, p2_b, d_o, Nn);
    zero_red_k<<<1, 512>>>();
    bn_stats_k<<<80, 256>>>(d_o);
    bn_final_k<<<1, 256>>>(pbn2_g, pbn2_b);
    bn_apply_k<<<Nn, HID>>>(d_o, d_h, 1);

    proj3_k<<<(Nn * 3 + 255) / 256, 256>>>(p3_W, p3_b, out);
}